// round 9
// baseline (speedup 1.0000x reference)
#include <cuda_runtime.h>

// CausalRevIN: B=16, T=8192, C=128, fp32.
// r8 structure (best: 1024 CTA-tiles, 4 warps, windowed lookback, atomic polls)
// + packed f32x2 arithmetic (FFMA2/FADD2/FMUL2) in the hot loops.

#define BB 16
#define TT 8192
#define TILE_T 128
#define SPW 32
#define SPB 64                  // tiles per series
#define NTILE (BB * SPB)        // 1024

#define STD_MIN 1e-5f
#define MAX_VAL 100.0f

typedef unsigned long long u64;

__device__ float4 g_aggA_nm[NTILE * 32];
__device__ float4 g_aggA_x [NTILE * 32];
__device__ float4 g_incA_nm[NTILE * 32];
__device__ float4 g_incA_x [NTILE * 32];
__device__ float4 g_aggC   [NTILE * 32];
__device__ float4 g_incC   [NTILE * 32];
__device__ int    g_stateA [NTILE];
__device__ int    g_stateC [NTILE];

__global__ void k_init() {
    int i = blockIdx.x * blockDim.x + threadIdx.x;
    if (i < NTILE) { g_stateA[i] = 0; g_stateC[i] = 0; }
}

__device__ __forceinline__ void f4add(float4& a, const float4 b) {
    a.x += b.x; a.y += b.y; a.z += b.z; a.w += b.w;
}

// ---- packed f32x2 helpers ----
__device__ __forceinline__ u64 pk(float lo, float hi) {
    u64 r; asm("mov.b64 %0, {%1, %2};" : "=l"(r) : "f"(lo), "f"(hi)); return r;
}
__device__ __forceinline__ void upk(u64 v, float& lo, float& hi) {
    asm("mov.b64 {%0, %1}, %2;" : "=f"(lo), "=f"(hi) : "l"(v));
}
__device__ __forceinline__ u64 add2(u64 a, u64 b) {
    u64 r; asm("add.rn.f32x2 %0, %1, %2;" : "=l"(r) : "l"(a), "l"(b)); return r;
}
__device__ __forceinline__ u64 mul2(u64 a, u64 b) {
    u64 r; asm("mul.rn.f32x2 %0, %1, %2;" : "=l"(r) : "l"(a), "l"(b)); return r;
}
__device__ __forceinline__ u64 fma2(u64 a, u64 b, u64 c) {
    u64 r; asm("fma.rn.f32x2 %0, %1, %2, %3;" : "=l"(r) : "l"(a), "l"(b), "l"(c)); return r;
}
__device__ __forceinline__ float rcpa(float x) {
    float r; asm("rcp.approx.f32 %0, %1;" : "=f"(r) : "f"(x)); return r;
}
__device__ __forceinline__ float rsqa(float x) {
    float r; asm("rsqrt.approx.f32 %0, %1;" : "=f"(r) : "f"(x)); return r;
}

__global__ void __launch_bounds__(128, 7) k_main(const float* __restrict__ x,
                                                 const float* __restrict__ m,
                                                 float* __restrict__ out) {
    __shared__ float4 s_a[128];
    __shared__ float4 s_b[128];

    const int tid  = threadIdx.x;
    const int tile = blockIdx.x;
    const int b    = tile >> 6;
    const int seg  = tile & (SPB - 1);
    const int w    = tid >> 5;
    const int l    = tid & 31;
    const int bbase = b << 6;

    const float4* __restrict__ x4 = (const float4*)x;
    const float4* __restrict__ m4 = (const float4*)m;
    float4* __restrict__ o4 = (float4*)out;
    const int rowbase = (b * TT + seg * TILE_T + w * SPW) * 32 + l;

    const u64 NEG1 = pk(-1.f, -1.f);

    // ================= Phase 1: load, pack mask bits, sum x =================
    u64 sx01 = 0, sx23 = 0;     // packed (0.0, 0.0)
    unsigned nb0 = 0, nb1 = 0, nb2 = 0, nb3 = 0;
    #pragma unroll 8
    for (int t = 0; t < SPW; t++) {
        float4 xv = x4[rowbase + t * 32];
        float4 mv = __ldcs(&m4[rowbase + t * 32]);
        sx01 = add2(sx01, pk(xv.x, xv.y));
        sx23 = add2(sx23, pk(xv.z, xv.w));
        if (mv.x == 0.f) nb0 |= 1u << t;
        if (mv.y == 0.f) nb1 |= 1u << t;
        if (mv.z == 0.f) nb2 |= 1u << t;
        if (mv.w == 0.f) nb3 |= 1u << t;
    }
    float4 snm = make_float4((float)__popc(nb0), (float)__popc(nb1),
                             (float)__popc(nb2), (float)__popc(nb3));
    float4 sx;
    upk(sx01, sx.x, sx.y); upk(sx23, sx.z, sx.w);
    s_a[tid] = snm; s_b[tid] = sx;
    __syncthreads();

    // exclusive prefix over warps (same lane) + CTA totals for warp 0
    float4 we_nm = make_float4(0.f, 0.f, 0.f, 0.f);
    float4 we_x  = make_float4(0.f, 0.f, 0.f, 0.f);
    for (int ww = 0; ww < w; ww++) { f4add(we_nm, s_a[ww * 32 + l]); f4add(we_x, s_b[ww * 32 + l]); }
    float4 tot_nm, tot_x;
    if (w == 0) {
        tot_nm = s_a[l];            tot_x = s_b[l];
        f4add(tot_nm, s_a[32 + l]); f4add(tot_x, s_b[32 + l]);
        f4add(tot_nm, s_a[64 + l]); f4add(tot_x, s_b[64 + l]);
        f4add(tot_nm, s_a[96 + l]); f4add(tot_x, s_b[96 + l]);
    }
    __syncthreads();

    // ================= Lookback A (warp 0) =================
    if (w == 0) {
        float4 ex_nm = make_float4(0.f, 0.f, 0.f, 0.f);
        float4 ex_x  = make_float4(0.f, 0.f, 0.f, 0.f);
        if (seg != 0) {
            g_aggA_nm[tile * 32 + l] = tot_nm;
            g_aggA_x [tile * 32 + l] = tot_x;
            __threadfence();
            __syncwarp();
            if (l == 0) atomicExch(&g_stateA[tile], 1);

            int p_end = seg;
            for (;;) {
                int cnt = p_end < 32 ? p_end : 32;
                int s = 2;
                if (l < cnt) {
                    int pp = bbase + p_end - 1 - l;
                    do { s = atomicAdd(&g_stateA[pp], 0); } while (s == 0);
                }
                unsigned incmask = __ballot_sync(0xffffffffu, (s == 2) && (l < cnt));
                __threadfence();
                int li = incmask ? (__ffs(incmask) - 1) : -1;
                int nagg = (li >= 0) ? li : cnt;
                for (int j = 0; j < nagg; j++) {
                    int pidx = (bbase + p_end - 1 - j) * 32 + l;
                    f4add(ex_nm, __ldcg(&g_aggA_nm[pidx]));
                    f4add(ex_x,  __ldcg(&g_aggA_x [pidx]));
                }
                if (li >= 0) {
                    int pidx = (bbase + p_end - 1 - li) * 32 + l;
                    f4add(ex_nm, __ldcg(&g_incA_nm[pidx]));
                    f4add(ex_x,  __ldcg(&g_incA_x [pidx]));
                    break;
                }
                p_end -= cnt;
            }
        }
        float4 in_nm = ex_nm, in_x = ex_x;
        f4add(in_nm, tot_nm); f4add(in_x, tot_x);
        g_incA_nm[tile * 32 + l] = in_nm;
        g_incA_x [tile * 32 + l] = in_x;
        __threadfence();
        __syncwarp();
        if (l == 0) atomicExch(&g_stateA[tile], 2);
        s_a[l] = ex_nm; s_b[l] = ex_x;
    }
    __syncthreads();
    float4 base_n = s_a[l], base_x = s_b[l];
    f4add(base_n, we_nm); f4add(base_x, we_x);

    // ================= Phase 2: local sum of ((x-mean)*nm)^2 (packed) =================
    u64 cn01 = pk(base_n.x, base_n.y), cn23 = pk(base_n.z, base_n.w);
    u64 cx01 = pk(base_x.x, base_x.y), cx23 = pk(base_x.z, base_x.w);
    u64 ls01 = 0, ls23 = 0;
    #pragma unroll 8
    for (int t = 0; t < SPW; t++) {
        float4 xv = x4[rowbase + t * 32];
        u64 xv01 = pk(xv.x, xv.y), xv23 = pk(xv.z, xv.w);
        u64 nm01 = pk((nb0 & (1u << t)) ? 1.f : 0.f, (nb1 & (1u << t)) ? 1.f : 0.f);
        u64 nm23 = pk((nb2 & (1u << t)) ? 1.f : 0.f, (nb3 & (1u << t)) ? 1.f : 0.f);
        cn01 = add2(cn01, nm01);  cn23 = add2(cn23, nm23);
        cx01 = add2(cx01, xv01);  cx23 = add2(cx23, xv23);
        float c0, c1, c2, c3;
        upk(cn01, c0, c1); upk(cn23, c2, c3);
        u64 rn01 = pk(rcpa(fmaxf(c0, 1.f)), rcpa(fmaxf(c1, 1.f)));
        u64 rn23 = pk(rcpa(fmaxf(c2, 1.f)), rcpa(fmaxf(c3, 1.f)));
        u64 mean01 = mul2(cx01, rn01), mean23 = mul2(cx23, rn23);
        u64 num01 = fma2(mean01, NEG1, xv01), num23 = fma2(mean23, NEG1, xv23);
        u64 sq01 = mul2(num01, num01), sq23 = mul2(num23, num23);
        ls01 = fma2(sq01, nm01, ls01);
        ls23 = fma2(sq23, nm23, ls23);
    }
    float4 lss;
    upk(ls01, lss.x, lss.y); upk(ls23, lss.z, lss.w);
    __syncthreads();
    s_a[tid] = lss;
    __syncthreads();
    float4 we_s = make_float4(0.f, 0.f, 0.f, 0.f);
    for (int ww = 0; ww < w; ww++) f4add(we_s, s_a[ww * 32 + l]);
    float4 tot_s;
    if (w == 0) {
        tot_s = s_a[l];
        f4add(tot_s, s_a[32 + l]); f4add(tot_s, s_a[64 + l]); f4add(tot_s, s_a[96 + l]);
    }
    __syncthreads();

    // ================= Lookback C (warp 0) =================
    if (w == 0) {
        float4 ex_s = make_float4(0.f, 0.f, 0.f, 0.f);
        if (seg != 0) {
            g_aggC[tile * 32 + l] = tot_s;
            __threadfence();
            __syncwarp();
            if (l == 0) atomicExch(&g_stateC[tile], 1);

            int p_end = seg;
            for (;;) {
                int cnt = p_end < 32 ? p_end : 32;
                int s = 2;
                if (l < cnt) {
                    int pp = bbase + p_end - 1 - l;
                    do { s = atomicAdd(&g_stateC[pp], 0); } while (s == 0);
                }
                unsigned incmask = __ballot_sync(0xffffffffu, (s == 2) && (l < cnt));
                __threadfence();
                int li = incmask ? (__ffs(incmask) - 1) : -1;
                int nagg = (li >= 0) ? li : cnt;
                for (int j = 0; j < nagg; j++)
                    f4add(ex_s, __ldcg(&g_aggC[(bbase + p_end - 1 - j) * 32 + l]));
                if (li >= 0) {
                    f4add(ex_s, __ldcg(&g_incC[(bbase + p_end - 1 - li) * 32 + l]));
                    break;
                }
                p_end -= cnt;
            }
        }
        float4 in_s = ex_s; f4add(in_s, tot_s);
        g_incC[tile * 32 + l] = in_s;
        __threadfence();
        __syncwarp();
        if (l == 0) atomicExch(&g_stateC[tile], 2);
        s_a[l] = ex_s;
    }
    __syncthreads();
    float4 base_s = s_a[l];
    f4add(base_s, we_s);

    // ================= Phase 3: normalize + clip, write out (packed) =================
    cn01 = pk(base_n.x, base_n.y); cn23 = pk(base_n.z, base_n.w);
    cx01 = pk(base_x.x, base_x.y); cx23 = pk(base_x.z, base_x.w);
    u64 cs01 = pk(base_s.x, base_s.y), cs23 = pk(base_s.z, base_s.w);
    const float VMIN = STD_MIN * STD_MIN;
    #pragma unroll 8
    for (int t = 0; t < SPW; t++) {
        float4 xv = __ldcs(&x4[rowbase + t * 32]);
        u64 xv01 = pk(xv.x, xv.y), xv23 = pk(xv.z, xv.w);
        u64 nm01 = pk((nb0 & (1u << t)) ? 1.f : 0.f, (nb1 & (1u << t)) ? 1.f : 0.f);
        u64 nm23 = pk((nb2 & (1u << t)) ? 1.f : 0.f, (nb3 & (1u << t)) ? 1.f : 0.f);
        cn01 = add2(cn01, nm01);  cn23 = add2(cn23, nm23);
        cx01 = add2(cx01, xv01);  cx23 = add2(cx23, xv23);
        float c0, c1, c2, c3;
        upk(cn01, c0, c1); upk(cn23, c2, c3);
        float r0 = rcpa(fmaxf(c0, 1.f)), r1 = rcpa(fmaxf(c1, 1.f));
        float r2 = rcpa(fmaxf(c2, 1.f)), r3 = rcpa(fmaxf(c3, 1.f));
        u64 rn01 = pk(r0, r1), rn23 = pk(r2, r3);
        u64 mean01 = mul2(cx01, rn01), mean23 = mul2(cx23, rn23);
        u64 num01 = fma2(mean01, NEG1, xv01), num23 = fma2(mean23, NEG1, xv23);
        u64 sq01 = mul2(num01, num01), sq23 = mul2(num23, num23);
        cs01 = fma2(sq01, nm01, cs01);
        cs23 = fma2(sq23, nm23, cs23);
        u64 var01 = mul2(cs01, rn01), var23 = mul2(cs23, rn23);
        float v0, v1, v2, v3;
        upk(var01, v0, v1); upk(var23, v2, v3);
        float s0 = (v0 > VMIN) ? rsqa(v0) : 1.f;
        float s1 = (v1 > VMIN) ? rsqa(v1) : 1.f;
        float s2 = (v2 > VMIN) ? rsqa(v2) : 1.f;
        float s3 = (v3 > VMIN) ? rsqa(v3) : 1.f;
        u64 res01 = mul2(num01, pk(s0, s1));
        u64 res23 = mul2(num23, pk(s2, s3));
        float4 ov;
        upk(res01, ov.x, ov.y); upk(res23, ov.z, ov.w);
        ov.x = fminf(fmaxf(ov.x, -MAX_VAL), MAX_VAL);
        ov.y = fminf(fmaxf(ov.y, -MAX_VAL), MAX_VAL);
        ov.z = fminf(fmaxf(ov.z, -MAX_VAL), MAX_VAL);
        ov.w = fminf(fmaxf(ov.w, -MAX_VAL), MAX_VAL);
        __stcs(&o4[rowbase + t * 32], ov);
    }
}

extern "C" void kernel_launch(void* const* d_in, const int* in_sizes, int n_in,
                              void* d_out, int out_size) {
    const float* x = (const float*)d_in[0];
    const float* m = (const float*)d_in[1];
    float* out = (float*)d_out;

    k_init<<<(NTILE + 255) / 256, 256>>>();
    k_main<<<NTILE, 128>>>(x, m, out);
}